// round 6
// baseline (speedup 1.0000x reference)
#include <cuda_runtime.h>
#include <cuda_bf16.h>

// SplineActivation: y[b][d] = sum_k Bspline_k(x[b][d]) * coeffs[d][k]
// Uniform cubic B-spline, branch-free truncated-power form:
//   t = 2x+2 in [0,4);  y(t) = P_0(t) + sum_{k=1..3} beta_k * ((t-k)+|t-k|)^3
// (C^2 continuity kills the lower-order jump terms; beta_k = dA_k/8.)
// Latency-oriented structure: persistent single-wave grid (8 x 148 CTAs,
// 8 CTAs/SM), rows strided by 148, chunks of 4 rows with all 4 LDG.128
// issued before compute (MLP=4), regs capped at 64 via launch_bounds.

#define INPUT_DIM 4096
#define BATCH_N   4096
#define TPB       128
#define GRID_Y    148
#define DQ        (INPUT_DIM / 4)

struct DimPoly { float A, B, C, D, b1, b2, b3; };

__device__ __forceinline__ float lead_coef(const float* e) {
    return fmaf(3.0f, e[1] - e[2], e[3] - e[0]);
}

__device__ __forceinline__ DimPoly build_dim(const float* e) {
    DimPoly q;
    float A0 = lead_coef(e + 0), A1 = lead_coef(e + 1);
    float A2 = lead_coef(e + 2), A3 = lead_coef(e + 3);
    q.A  = A0;
    q.B  = fmaf(-6.0f, e[1], 3.0f * (e[0] + e[2]));
    q.C  = 3.0f * (e[2] - e[0]);
    q.D  = fmaf(4.0f, e[1], e[0] + e[2]);
    q.b1 = (A1 - A0) * 0.125f;
    q.b2 = (A2 - A1) * 0.125f;
    q.b3 = (A3 - A2) * 0.125f;
    return q;
}

__device__ __forceinline__ float eval_dim(float xv, const DimPoly& q) {
    float t  = fmaf(xv, 2.0f, 2.0f);
    float r1 = fmaf(xv, 2.0f, 1.0f);          // t-1
    float r2 = xv + xv;                       // t-2
    float r3 = fmaf(xv, 2.0f, -1.0f);         // t-3
    float p1 = r1 + fabsf(r1);
    float p2 = r2 + fabsf(r2);
    float p3 = r3 + fabsf(r3);
    float h  = fmaf(fmaf(fmaf(q.A, t, q.B), t, q.C), t, q.D);
    h = fmaf(q.b1 * p1, p1 * p1, h);
    h = fmaf(q.b2 * p2, p2 * p2, h);
    h = fmaf(q.b3 * p3, p3 * p3, h);
    return h;
}

__device__ __forceinline__ float4 eval4(float4 xv, const DimPoly* q) {
    float4 ov;
    ov.x = eval_dim(xv.x, q[0]);
    ov.y = eval_dim(xv.y, q[1]);
    ov.z = eval_dim(xv.z, q[2]);
    ov.w = eval_dim(xv.w, q[3]);
    return ov;
}

__global__ void __launch_bounds__(TPB, 8)
spline_activation_kernel(const float4* __restrict__ x,
                         const float4* __restrict__ coeffs4,
                         float4* __restrict__ out) {
    int dq = blockIdx.x * TPB + threadIdx.x;        // 0..1023 column-quad

    // Load 28 coeffs (4 dims x 7) as 7 x LDG.128, scale by 1/6.
    const float k6 = 1.0f / 6.0f;
    float c[28];
    const float4* cp = coeffs4 + (size_t)dq * 7;
#pragma unroll
    for (int i = 0; i < 7; ++i) {
        float4 v = __ldg(cp + i);
        c[4 * i + 0] = v.x * k6;
        c[4 * i + 1] = v.y * k6;
        c[4 * i + 2] = v.z * k6;
        c[4 * i + 3] = v.w * k6;
    }
    DimPoly q[4] = { build_dim(c + 0),  build_dim(c + 7),
                     build_dim(c + 14), build_dim(c + 21) };

    // Persistent: this block handles rows r = blockIdx.y + GRID_Y * i.
    int row0 = blockIdx.y;
    int cnt  = (BATCH_N - row0 + GRID_Y - 1) / GRID_Y;     // 27 or 28
    const size_t STEP = (size_t)GRID_Y * DQ;               // row stride (f4)
    size_t idx = (size_t)row0 * DQ + dq;

    int i = 0;
    for (; i + 4 <= cnt; i += 4) {
        // phase 1: issue 4 independent LDG.128
        float4 a0 = __ldg(x + idx);
        float4 a1 = __ldg(x + idx + STEP);
        float4 a2 = __ldg(x + idx + 2 * STEP);
        float4 a3 = __ldg(x + idx + 3 * STEP);
        // phase 2: compute + store
        out[idx]            = eval4(a0, q);
        out[idx + STEP]     = eval4(a1, q);
        out[idx + 2 * STEP] = eval4(a2, q);
        out[idx + 3 * STEP] = eval4(a3, q);
        idx += 4 * STEP;
    }
    for (; i < cnt; ++i) {
        float4 a = __ldg(x + idx);
        out[idx] = eval4(a, q);
        idx += STEP;
    }
}

extern "C" void kernel_launch(void* const* d_in, const int* in_sizes, int n_in,
                              void* d_out, int out_size) {
    const float4* x      = (const float4*)d_in[0];   // (4096, 4096) fp32
    const float4* coeffs = (const float4*)d_in[1];   // (4096, 7) fp32
    float4*       out    = (float4*)d_out;           // (4096, 4096) fp32

    dim3 grid(DQ / TPB, GRID_Y, 1);                  // (8, 148) = 1184 CTAs
    spline_activation_kernel<<<grid, TPB>>>(x, coeffs, out);
}

// round 7
// speedup vs baseline: 1.1294x; 1.1294x over previous
#include <cuda_runtime.h>
#include <cuda_bf16.h>

// SplineActivation: y[b][d] = sum_k Bspline_k(x[b][d]) * coeffs[d][k]
// Uniform cubic B-spline, branch-free truncated-power form:
//   t = 2x+2 in [0,4);  y(t) = P_0(t) + sum_{k=1..3} beta_k * ((t-k)+|t-k|)^3
// Memory-path round: x is L2-resident across graph replays (64MB vs 126MB L2);
// out is write-only. Store with evict-first (__stcs) so writes don't evict x,
// load x L2-only (__ldcg), and software-pipeline 2 rows ahead so loads stay
// in flight across the store phase.

#define INPUT_DIM 4096
#define BATCH_N   4096
#define TPB       128
#define GRID_Y    148
#define DQ        (INPUT_DIM / 4)

struct DimPoly { float A, B, C, D, b1, b2, b3; };

__device__ __forceinline__ float lead_coef(const float* e) {
    return fmaf(3.0f, e[1] - e[2], e[3] - e[0]);
}

__device__ __forceinline__ DimPoly build_dim(const float* e) {
    DimPoly q;
    float A0 = lead_coef(e + 0), A1 = lead_coef(e + 1);
    float A2 = lead_coef(e + 2), A3 = lead_coef(e + 3);
    q.A  = A0;
    q.B  = fmaf(-6.0f, e[1], 3.0f * (e[0] + e[2]));
    q.C  = 3.0f * (e[2] - e[0]);
    q.D  = fmaf(4.0f, e[1], e[0] + e[2]);
    q.b1 = (A1 - A0) * 0.125f;
    q.b2 = (A2 - A1) * 0.125f;
    q.b3 = (A3 - A2) * 0.125f;
    return q;
}

__device__ __forceinline__ float eval_dim(float xv, const DimPoly& q) {
    float t  = fmaf(xv, 2.0f, 2.0f);
    float r1 = fmaf(xv, 2.0f, 1.0f);          // t-1
    float r2 = xv + xv;                       // t-2
    float r3 = fmaf(xv, 2.0f, -1.0f);         // t-3
    float p1 = r1 + fabsf(r1);
    float p2 = r2 + fabsf(r2);
    float p3 = r3 + fabsf(r3);
    float h  = fmaf(fmaf(fmaf(q.A, t, q.B), t, q.C), t, q.D);
    h = fmaf(q.b1 * p1, p1 * p1, h);
    h = fmaf(q.b2 * p2, p2 * p2, h);
    h = fmaf(q.b3 * p3, p3 * p3, h);
    return h;
}

__device__ __forceinline__ float4 eval4(float4 xv, const DimPoly* q) {
    float4 ov;
    ov.x = eval_dim(xv.x, q[0]);
    ov.y = eval_dim(xv.y, q[1]);
    ov.z = eval_dim(xv.z, q[2]);
    ov.w = eval_dim(xv.w, q[3]);
    return ov;
}

__global__ void __launch_bounds__(TPB)
spline_activation_kernel(const float4* __restrict__ x,
                         const float4* __restrict__ coeffs4,
                         float4* __restrict__ out) {
    int dq = blockIdx.x * TPB + threadIdx.x;        // 0..1023 column-quad

    // Load 28 coeffs (4 dims x 7) as 7 x LDG.128, scale by 1/6.
    const float k6 = 1.0f / 6.0f;
    float c[28];
    const float4* cp = coeffs4 + (size_t)dq * 7;
#pragma unroll
    for (int i = 0; i < 7; ++i) {
        float4 v = __ldg(cp + i);
        c[4 * i + 0] = v.x * k6;
        c[4 * i + 1] = v.y * k6;
        c[4 * i + 2] = v.z * k6;
        c[4 * i + 3] = v.w * k6;
    }
    DimPoly q[4] = { build_dim(c + 0),  build_dim(c + 7),
                     build_dim(c + 14), build_dim(c + 21) };

    // Persistent: this block handles rows r = blockIdx.y + GRID_Y * i.
    int row0 = blockIdx.y;
    int cnt  = (BATCH_N - row0 + GRID_Y - 1) / GRID_Y;     // 27 or 28
    const size_t STEP = (size_t)GRID_Y * DQ;               // row stride (f4)
    size_t idx = (size_t)row0 * DQ + dq;

    // Software pipeline, 2 rows per stage, prefetch next stage (clamped).
    float4 a0 = __ldcg(x + idx);
    float4 a1 = __ldcg(x + idx + STEP);                    // cnt >= 27 always

    int i = 0;
    for (; i + 2 <= cnt; i += 2) {
        // prefetch next pair (clamp offsets so we never read OOB)
        size_t o2 = (i + 2 < cnt) ? 2 * STEP : 0;
        size_t o3 = (i + 3 < cnt) ? 3 * STEP : 0;
        float4 n0 = __ldcg(x + idx + o2);
        float4 n1 = __ldcg(x + idx + o3);
        // compute + streaming store (evict-first: keep x resident in L2)
        __stcs(out + idx,        eval4(a0, q));
        __stcs(out + idx + STEP, eval4(a1, q));
        a0 = n0; a1 = n1;
        idx += 2 * STEP;
    }
    if (i < cnt)                                            // odd tail (cnt=27)
        __stcs(out + idx, eval4(a0, q));
}

extern "C" void kernel_launch(void* const* d_in, const int* in_sizes, int n_in,
                              void* d_out, int out_size) {
    const float4* x      = (const float4*)d_in[0];   // (4096, 4096) fp32
    const float4* coeffs = (const float4*)d_in[1];   // (4096, 7) fp32
    float4*       out    = (float4*)d_out;           // (4096, 4096) fp32

    dim3 grid(DQ / TPB, GRID_Y, 1);                  // (8, 148) = 1184 CTAs
    spline_activation_kernel<<<grid, TPB>>>(x, coeffs, out);
}

// round 8
// speedup vs baseline: 1.1351x; 1.0051x over previous
#include <cuda_runtime.h>
#include <cuda_bf16.h>

// SplineActivation: y[b][d] = sum_k Bspline_k(x[b][d]) * coeffs[d][k]
// Uniform cubic B-spline, branch-free truncated-power form:
//   t = 2x+2 in [0,4);  y(t) = P_0(t) + sum_{k=1..3} beta_k * ((t-k)+|t-k|)^3
// Occupancy round: 2 dims per thread (one f32x2 lane pair), packed-pair math
// via fma.rn.f32x2 so per-thread constant state is 7 u64 regs. ~40 regs ->
// ~48 warps/SM vs the 27 that pinned R4-R7 at 22us. Persistent 1-wave grid,
// __ldcg loads (L2-resident x) + __stcs stores (evict-first, write-only out),
// 2-stage software pipeline.

#define INPUT_DIM 4096
#define BATCH_N   4096
#define TPB       128
#define GRID_Y    148
#define DP2       (INPUT_DIM / 2)      // 2048 column-pairs

typedef unsigned long long u64;

__device__ __forceinline__ u64 pack2(float lo, float hi) {
    u64 r; asm("mov.b64 %0, {%1, %2};" : "=l"(r) : "f"(lo), "f"(hi)); return r;
}
__device__ __forceinline__ u64 fma2(u64 a, u64 b, u64 c) {
    u64 d; asm("fma.rn.f32x2 %0, %1, %2, %3;" : "=l"(d) : "l"(a), "l"(b), "l"(c)); return d;
}
__device__ __forceinline__ u64 mul2(u64 a, u64 b) {
    u64 d; asm("mul.rn.f32x2 %0, %1, %2;" : "=l"(d) : "l"(a), "l"(b)); return d;
}
__device__ __forceinline__ u64 add2(u64 a, u64 b) {
    u64 d; asm("add.rn.f32x2 %0, %1, %2;" : "=l"(d) : "l"(a), "l"(b)); return d;
}
__device__ __forceinline__ u64 abs2(u64 a) { return a & 0x7FFFFFFF7FFFFFFFULL; }

struct PairPoly { u64 A, B, C, D, b1, b2, b3; };   // lanes = the 2 dims

__device__ __forceinline__ u64 eval_pair(u64 x2, const PairPoly& q) {
    const u64 two2 = 0x4000000040000000ULL;   // {2,2}
    const u64 one2 = 0x3F8000003F800000ULL;   // {1,1}
    const u64 n1_2 = 0xBF800000BF800000ULL;   // {-1,-1}
    u64 t  = fma2(x2, two2, two2);            // 2x+2
    u64 r1 = fma2(x2, two2, one2);            // t-1
    u64 r2 = add2(x2, x2);                    // t-2
    u64 r3 = fma2(x2, two2, n1_2);            // t-3
    u64 p1 = add2(r1, abs2(r1));              // 2*(t-1)_+
    u64 p2 = add2(r2, abs2(r2));
    u64 p3 = add2(r3, abs2(r3));
    u64 h  = fma2(fma2(fma2(q.A, t, q.B), t, q.C), t, q.D);
    h = fma2(mul2(q.b1, p1), mul2(p1, p1), h);
    h = fma2(mul2(q.b2, p2), mul2(p2, p2), h);
    h = fma2(mul2(q.b3, p3), mul2(p3, p3), h);
    return h;
}

struct DimPoly { float A, B, C, D, b1, b2, b3; };

__device__ __forceinline__ float lead_coef(const float* e) {
    return fmaf(3.0f, e[1] - e[2], e[3] - e[0]);
}

__device__ __forceinline__ DimPoly build_dim(const float* e) {
    DimPoly q;
    float A0 = lead_coef(e + 0), A1 = lead_coef(e + 1);
    float A2 = lead_coef(e + 2), A3 = lead_coef(e + 3);
    q.A  = A0;
    q.B  = fmaf(-6.0f, e[1], 3.0f * (e[0] + e[2]));
    q.C  = 3.0f * (e[2] - e[0]);
    q.D  = fmaf(4.0f, e[1], e[0] + e[2]);
    q.b1 = (A1 - A0) * 0.125f;
    q.b2 = (A2 - A1) * 0.125f;
    q.b3 = (A3 - A2) * 0.125f;
    return q;
}

__global__ void __launch_bounds__(TPB)
spline_activation_kernel(const u64* __restrict__ x,
                         const float2* __restrict__ coeffs2,
                         u64* __restrict__ out) {
    int dq2 = blockIdx.x * TPB + threadIdx.x;        // 0..2047 column-pair

    // 14 coeffs (2 dims x 7), 8B-aligned (14 floats * dq2 = 56B*dq2).
    const float k6 = 1.0f / 6.0f;
    float c[14];
    const float2* cp = coeffs2 + (size_t)dq2 * 7;
#pragma unroll
    for (int i = 0; i < 7; ++i) {
        float2 v = __ldg(cp + i);
        c[2 * i + 0] = v.x * k6;
        c[2 * i + 1] = v.y * k6;
    }
    DimPoly s0 = build_dim(c), s1 = build_dim(c + 7);
    PairPoly q;
    q.A  = pack2(s0.A,  s1.A);
    q.B  = pack2(s0.B,  s1.B);
    q.C  = pack2(s0.C,  s1.C);
    q.D  = pack2(s0.D,  s1.D);
    q.b1 = pack2(s0.b1, s1.b1);
    q.b2 = pack2(s0.b2, s1.b2);
    q.b3 = pack2(s0.b3, s1.b3);

    // Persistent: rows r = blockIdx.y + GRID_Y * i.
    int row0 = blockIdx.y;
    int cnt  = (BATCH_N - row0 + GRID_Y - 1) / GRID_Y;     // 27 or 28
    const size_t STEP = (size_t)GRID_Y * DP2;              // row stride (u64)
    size_t idx = (size_t)row0 * DP2 + dq2;

    // 2-stage pipeline, 2 rows per stage (cnt >= 27 so initial loads safe).
    u64 a0 = __ldcg(x + idx);
    u64 a1 = __ldcg(x + idx + STEP);

    int i = 0;
    for (; i + 2 <= cnt; i += 2) {
        size_t o2 = (i + 2 < cnt) ? 2 * STEP : 0;
        size_t o3 = (i + 3 < cnt) ? 3 * STEP : 0;
        u64 n0 = __ldcg(x + idx + o2);
        u64 n1 = __ldcg(x + idx + o3);
        __stcs(out + idx,        eval_pair(a0, q));
        __stcs(out + idx + STEP, eval_pair(a1, q));
        a0 = n0; a1 = n1;
        idx += 2 * STEP;
    }
    if (i < cnt)                                            // odd tail (cnt=27)
        __stcs(out + idx, eval_pair(a0, q));
}

extern "C" void kernel_launch(void* const* d_in, const int* in_sizes, int n_in,
                              void* d_out, int out_size) {
    const u64*    x      = (const u64*)d_in[0];      // (4096, 4096) fp32
    const float2* coeffs = (const float2*)d_in[1];   // (4096, 7) fp32
    u64*          out    = (u64*)d_out;              // (4096, 4096) fp32

    dim3 grid(DP2 / TPB, GRID_Y, 1);                 // (16, 148) = 2368 CTAs
    spline_activation_kernel<<<grid, TPB>>>(x, coeffs, out);
}